// round 1
// baseline (speedup 1.0000x reference)
#include <cuda_runtime.h>
#include <math_constants.h>

#define BATCH 4
#define NSEQ  2048
#define EDIM  1024
#define NH    16
#define CHD   64
#define MTOT  (BATCH * NSEQ)   // 8192

// Scratch buffers (allocation-free: __device__ globals).
__device__ float g_q[MTOT * EDIM];     // [b, h, n, c]
__device__ float g_k[MTOT * EDIM];     // [b, h, n, c]
__device__ float g_v[MTOT * EDIM];     // [b, h, n, c]
__device__ float g_attn[MTOT * EDIM];  // [b, n, h*c]  (ready for out-proj)

// ---------------------------------------------------------------------------
// NT SGEMM: C[M,N] = A[M,K] * W[N,K]^T + bias, K = N = EDIM, M = MTOT.
// 64x64 block tile, BK=16, 256 threads, 4x4 register tile per thread.
// QKV=1: scatter output into [b, h, n, c] layout (one head per block column,
//        since BN=64=CHD and N=EDIM).
// QKV=0: plain row-major [M, N] output.
// ---------------------------------------------------------------------------
template <int QKV>
__global__ __launch_bounds__(256)
void gemm_nt_kernel(const float* __restrict__ A, const float* __restrict__ W,
                    const float* __restrict__ bias, float* __restrict__ out)
{
    __shared__ float As[16][64];
    __shared__ float Bs[16][64];

    const int tid = threadIdx.x;
    const int tx  = tid & 15;     // 0..15 -> N
    const int ty  = tid >> 4;     // 0..15 -> M
    const int m0  = blockIdx.y << 6;
    const int n0  = blockIdx.x << 6;

    const int lr = tid >> 2;      // 0..63 : tile row for loads
    const int ls = tid & 3;       // 0..3  : float4 segment within BK=16

    const float* Aptr = A + (size_t)(m0 + lr) * EDIM + ls * 4;
    const float* Wptr = W + (size_t)(n0 + lr) * EDIM + ls * 4;

    float acc[4][4];
#pragma unroll
    for (int i = 0; i < 4; i++)
#pragma unroll
        for (int j = 0; j < 4; j++) acc[i][j] = 0.f;

    for (int k0 = 0; k0 < EDIM; k0 += 16) {
        float4 a = *(const float4*)(Aptr + k0);
        float4 b = *(const float4*)(Wptr + k0);
        As[ls * 4 + 0][lr] = a.x; As[ls * 4 + 1][lr] = a.y;
        As[ls * 4 + 2][lr] = a.z; As[ls * 4 + 3][lr] = a.w;
        Bs[ls * 4 + 0][lr] = b.x; Bs[ls * 4 + 1][lr] = b.y;
        Bs[ls * 4 + 2][lr] = b.z; Bs[ls * 4 + 3][lr] = b.w;
        __syncthreads();

#pragma unroll
        for (int k = 0; k < 16; k++) {
            float4 av = *(const float4*)&As[k][ty << 2];
            float4 bv = *(const float4*)&Bs[k][tx << 2];
            float ar[4] = {av.x, av.y, av.z, av.w};
            float br[4] = {bv.x, bv.y, bv.z, bv.w};
#pragma unroll
            for (int i = 0; i < 4; i++)
#pragma unroll
                for (int j = 0; j < 4; j++)
                    acc[i][j] = fmaf(ar[i], br[j], acc[i][j]);
        }
        __syncthreads();
    }

    float4 bb = *(const float4*)&bias[n0 + (tx << 2)];
    const float bj[4] = {bb.x, bb.y, bb.z, bb.w};

#pragma unroll
    for (int i = 0; i < 4; i++) {
        const int m = m0 + (ty << 2) + i;
        float4 v;
        v.x = acc[i][0] + bj[0];
        v.y = acc[i][1] + bj[1];
        v.z = acc[i][2] + bj[2];
        v.w = acc[i][3] + bj[3];
        if (QKV) {
            // column tile == one head (BN == CHD): h = blockIdx.x
            const int b = m >> 11;            // m / NSEQ
            const int n = m & (NSEQ - 1);
            const int h = blockIdx.x;
            *(float4*)&out[(((size_t)(b * NH + h) * NSEQ + n) << 6) + (tx << 2)] = v;
        } else {
            *(float4*)&out[(size_t)m * EDIM + n0 + (tx << 2)] = v;
        }
    }
}

// ---------------------------------------------------------------------------
// Flash-style attention, fp32. One block = one (b,h) x 64-query tile.
// 256 threads as 16x16; each thread holds a 4x4 tile of S and of O.
// Online softmax with width-16 shuffle reductions (lanes sharing ty).
// ---------------------------------------------------------------------------
#define SLD 68   // smem row stride (floats): pad 64 -> 68, keeps 16B alignment

__global__ __launch_bounds__(256)
void attn_kernel()
{
    extern __shared__ float smem[];
    float* Qs = smem;                 // [64][SLD]
    float* Ks = smem + 64 * SLD;      // [64][SLD]
    float* Vs = smem + 2 * 64 * SLD;  // [64][SLD]
    float* Ps = smem + 3 * 64 * SLD;  // [64][SLD], transposed: Ps[j][i]

    const int tid = threadIdx.x;
    const int tx  = tid & 15;
    const int ty  = tid >> 4;
    const int bh  = blockIdx.y;           // b*NH + h
    const int q0  = blockIdx.x << 6;

    const float* qh = g_q + (size_t)bh * NSEQ * CHD;
    const float* kh = g_k + (size_t)bh * NSEQ * CHD;
    const float* vh = g_v + (size_t)bh * NSEQ * CHD;

    const int lr = tid >> 2;              // 0..63 : tile row for loads
    const int lc = (tid & 3) * 16;        // col base (4 float4s each)

    // Load Q tile, folding in softmax scale 1/sqrt(64) = 0.125.
#pragma unroll
    for (int u = 0; u < 4; u++) {
        float4 v = *(const float4*)&qh[(size_t)(q0 + lr) * CHD + lc + u * 4];
        v.x *= 0.125f; v.y *= 0.125f; v.z *= 0.125f; v.w *= 0.125f;
        *(float4*)&Qs[lr * SLD + lc + u * 4] = v;
    }

    float m_run[4], l_run[4], o[4][4];
#pragma unroll
    for (int i = 0; i < 4; i++) {
        m_run[i] = -CUDART_INF_F;
        l_run[i] = 0.f;
#pragma unroll
        for (int j = 0; j < 4; j++) o[i][j] = 0.f;
    }

    for (int kv0 = 0; kv0 < NSEQ; kv0 += 64) {
        __syncthreads();   // previous iteration done reading Ks/Vs/Ps
#pragma unroll
        for (int u = 0; u < 4; u++) {
            *(float4*)&Ks[lr * SLD + lc + u * 4] =
                *(const float4*)&kh[(size_t)(kv0 + lr) * CHD + lc + u * 4];
            *(float4*)&Vs[lr * SLD + lc + u * 4] =
                *(const float4*)&vh[(size_t)(kv0 + lr) * CHD + lc + u * 4];
        }
        __syncthreads();

        // S = (Q*scale) @ K^T for this tile: 4x4 per thread
        float s[4][4];
#pragma unroll
        for (int i = 0; i < 4; i++)
#pragma unroll
            for (int j = 0; j < 4; j++) s[i][j] = 0.f;

#pragma unroll 4
        for (int c = 0; c < CHD; c += 4) {
            float4 qv[4], kv[4];
#pragma unroll
            for (int i = 0; i < 4; i++)
                qv[i] = *(const float4*)&Qs[((ty << 2) + i) * SLD + c];
#pragma unroll
            for (int j = 0; j < 4; j++)
                kv[j] = *(const float4*)&Ks[((tx << 2) + j) * SLD + c];
#pragma unroll
            for (int i = 0; i < 4; i++)
#pragma unroll
                for (int j = 0; j < 4; j++) {
                    s[i][j] = fmaf(qv[i].x, kv[j].x, s[i][j]);
                    s[i][j] = fmaf(qv[i].y, kv[j].y, s[i][j]);
                    s[i][j] = fmaf(qv[i].z, kv[j].z, s[i][j]);
                    s[i][j] = fmaf(qv[i].w, kv[j].w, s[i][j]);
                }
        }

        // Online softmax per row (row owned by the 16 lanes sharing ty).
#pragma unroll
        for (int i = 0; i < 4; i++) {
            float tmax = fmaxf(fmaxf(s[i][0], s[i][1]), fmaxf(s[i][2], s[i][3]));
#pragma unroll
            for (int off = 8; off > 0; off >>= 1)
                tmax = fmaxf(tmax, __shfl_xor_sync(0xffffffffu, tmax, off, 16));
            const float mn    = fmaxf(m_run[i], tmax);
            const float alpha = __expf(m_run[i] - mn);
            float rs = 0.f;
#pragma unroll
            for (int j = 0; j < 4; j++) {
                s[i][j] = __expf(s[i][j] - mn);
                rs += s[i][j];
            }
#pragma unroll
            for (int off = 8; off > 0; off >>= 1)
                rs += __shfl_xor_sync(0xffffffffu, rs, off, 16);
            l_run[i] = l_run[i] * alpha + rs;
            m_run[i] = mn;
#pragma unroll
            for (int j = 0; j < 4; j++) o[i][j] *= alpha;
        }

        // Exchange P transposed: Ps[j][i]
#pragma unroll
        for (int i = 0; i < 4; i++)
#pragma unroll
            for (int j = 0; j < 4; j++)
                Ps[((tx << 2) + j) * SLD + (ty << 2) + i] = s[i][j];
        __syncthreads();

        // O += P @ V
#pragma unroll 4
        for (int j = 0; j < 64; j++) {
            float4 pv = *(const float4*)&Ps[j * SLD + (ty << 2)];
            float4 vv = *(const float4*)&Vs[j * SLD + (tx << 2)];
            float pr[4] = {pv.x, pv.y, pv.z, pv.w};
            float vr[4] = {vv.x, vv.y, vv.z, vv.w};
#pragma unroll
            for (int i = 0; i < 4; i++)
#pragma unroll
                for (int c = 0; c < 4; c++)
                    o[i][c] = fmaf(pr[i], vr[c], o[i][c]);
        }
    }

    // Normalize and write to [b, n, h*c] layout for the output projection.
    const int b = bh >> 4;
    const int h = bh & 15;
#pragma unroll
    for (int i = 0; i < 4; i++) {
        const float inv = 1.f / l_run[i];
        const int n = q0 + (ty << 2) + i;
        float4 v;
        v.x = o[i][0] * inv; v.y = o[i][1] * inv;
        v.z = o[i][2] * inv; v.w = o[i][3] * inv;
        *(float4*)&g_attn[(((size_t)b * NSEQ + n) * NH + h) * CHD + (tx << 2)] = v;
    }
}

// ---------------------------------------------------------------------------
// Launch
// ---------------------------------------------------------------------------
extern "C" void kernel_launch(void* const* d_in, const int* in_sizes, int n_in,
                              void* d_out, int out_size)
{
    const float* x  = (const float*)d_in[0];
    const float* Wq = (const float*)d_in[1];
    const float* bq = (const float*)d_in[2];
    const float* Wk = (const float*)d_in[3];
    const float* bk = (const float*)d_in[4];
    const float* Wv = (const float*)d_in[5];
    const float* bv = (const float*)d_in[6];
    const float* Wo = (const float*)d_in[7];
    const float* bo = (const float*)d_in[8];
    float* out = (float*)d_out;

    float *qp, *kp, *vp, *ap;
    cudaGetSymbolAddress((void**)&qp, g_q);
    cudaGetSymbolAddress((void**)&kp, g_k);
    cudaGetSymbolAddress((void**)&vp, g_v);
    cudaGetSymbolAddress((void**)&ap, g_attn);

    const int ATTN_SMEM = 4 * 64 * SLD * sizeof(float);  // 69632 B
    cudaFuncSetAttribute(attn_kernel,
                         cudaFuncAttributeMaxDynamicSharedMemorySize, ATTN_SMEM);

    dim3 ggrid(EDIM / 64, MTOT / 64);  // (16, 128)
    gemm_nt_kernel<1><<<ggrid, 256>>>(x, Wq, bq, qp);
    gemm_nt_kernel<1><<<ggrid, 256>>>(x, Wk, bk, kp);
    gemm_nt_kernel<1><<<ggrid, 256>>>(x, Wv, bv, vp);

    attn_kernel<<<dim3(NSEQ / 64, BATCH * NH), 256, ATTN_SMEM>>>();

    gemm_nt_kernel<0><<<ggrid, 256>>>(ap, Wo, bo, out);
}

// round 3
// speedup vs baseline: 4.9995x; 4.9995x over previous
#include <cuda_runtime.h>
#include <math_constants.h>
#include <cstdint>

#define BATCH 4
#define NSEQ  2048
#define EDIM  1024
#define NH    16
#define CHD   64
#define MTOT  (BATCH * NSEQ)   // 8192

// Scratch (allocation-free: __device__ globals).
__device__ float g_q[MTOT * EDIM];        // [b, h, n, c]  (tf32-rounded)
__device__ float g_k[MTOT * EDIM];        // [b, h, n, c]  (tf32-rounded)
__device__ float g_v[MTOT * EDIM];        // [b, h, n, c]  (tf32-rounded)
__device__ float g_attn[MTOT * EDIM];     // [b, n, h*c]   (tf32-rounded)
__device__ float g_xr[MTOT * EDIM];       // x, tf32-rounded
__device__ float g_wr[4][EDIM * EDIM];    // Wq,Wk,Wv,Wo, tf32-rounded

// ---------------------------------------------------------------------------
// Helpers
// ---------------------------------------------------------------------------
__device__ __forceinline__ uint32_t smem_u32(const void* p) {
    uint32_t a;
    asm("{ .reg .u64 t; cvta.to.shared.u64 t, %1; cvt.u32.u64 %0, t; }"
        : "=r"(a) : "l"(p));
    return a;
}

__device__ __forceinline__ float rtf32(float x) {
    uint32_t r;
    asm("cvt.rna.tf32.f32 %0, %1;" : "=r"(r) : "f"(x));
    return __uint_as_float(r);
}

__device__ __forceinline__ uint32_t fbits(float x) { return __float_as_uint(x); }

// D += A @ B  (m16n8k8, tf32 in, f32 accumulate)
__device__ __forceinline__ void mma8(float* c, const uint32_t* a, const uint32_t* b) {
    asm volatile(
        "mma.sync.aligned.m16n8k8.row.col.f32.tf32.tf32.f32 "
        "{%0,%1,%2,%3}, {%4,%5,%6,%7}, {%8,%9}, {%0,%1,%2,%3};"
        : "+f"(c[0]), "+f"(c[1]), "+f"(c[2]), "+f"(c[3])
        : "r"(a[0]), "r"(a[1]), "r"(a[2]), "r"(a[3]), "r"(b[0]), "r"(b[1]));
}

#define CP_ASYNC16(dst, src) \
    asm volatile("cp.async.cg.shared.global [%0], [%1], 16;" :: "r"(dst), "l"(src))
#define CP_COMMIT() asm volatile("cp.async.commit_group;" ::: "memory")
#define CP_WAIT1()  asm volatile("cp.async.wait_group 1;" ::: "memory")

// ---------------------------------------------------------------------------
// tf32 pre-round kernel (element-wise, float4)
// ---------------------------------------------------------------------------
__global__ void round_tf32_kernel(const float* __restrict__ in,
                                  float* __restrict__ out, int n4)
{
    int i = blockIdx.x * blockDim.x + threadIdx.x;
    if (i < n4) {
        float4 v = ((const float4*)in)[i];
        v.x = rtf32(v.x); v.y = rtf32(v.y); v.z = rtf32(v.z); v.w = rtf32(v.w);
        ((float4*)out)[i] = v;
    }
}

// ---------------------------------------------------------------------------
// tf32 mma.sync NT GEMM: C[M,N] = A[M,K] @ W[N,K]^T + bias
// M=8192, N=K=1024. 128x128 CTA tile, 8 warps (4m x 2n -> 32x64 warp tiles),
// BK=32, double-buffered cp.async. Smem k-stride 36 (conflict-free frags).
// QKV=1: round + scatter into [b,h,n,c].  QKV=0: plain row-major.
// ---------------------------------------------------------------------------
#define GS        36
#define STAGE_FL  (2 * 128 * GS)          // A + B per stage (floats)
#define GSMEM     (2 * STAGE_FL * 4)      // 73728 bytes

template <int QKV>
__global__ __launch_bounds__(256)
void gemm_mma(const float* __restrict__ A, const float* __restrict__ W,
              const float* __restrict__ bias, float* __restrict__ out)
{
    extern __shared__ __align__(16) float sm[];
    const uint32_t sm0 = smem_u32(sm);
    const int tid = threadIdx.x, lane = tid & 31, wid = tid >> 5;
    const int g = lane >> 2, t = lane & 3;
    const int m0 = blockIdx.y << 7, n0 = blockIdx.x << 7;
    const int wm = (wid >> 1) << 5;          // 0,32,64,96
    const int wn = (wid & 1) << 6;           // 0,64

    // loader: A tile 128x32 (1024 f4) + B tile 128x32 -> 8 f4 per thread
    auto load_slab = [&](int s, int buf) {
        const int k0 = s << 5;
        const uint32_t base = sm0 + (uint32_t)buf * (STAGE_FL * 4);
#pragma unroll
        for (int i = 0; i < 4; i++) {
            const int idx = tid + (i << 8);        // 0..1023
            const int row = idx >> 3, seg = idx & 7;
            const uint32_t so = (uint32_t)(row * GS + seg * 4) * 4;
            CP_ASYNC16(base + so,
                       A + (size_t)(m0 + row) * EDIM + k0 + seg * 4);
            CP_ASYNC16(base + (uint32_t)(128 * GS * 4) + so,
                       W + (size_t)(n0 + row) * EDIM + k0 + seg * 4);
        }
        CP_COMMIT();
    };

    float acc[2][8][4];
#pragma unroll
    for (int mt = 0; mt < 2; mt++)
#pragma unroll
        for (int nt = 0; nt < 8; nt++)
#pragma unroll
            for (int r = 0; r < 4; r++) acc[mt][nt][r] = 0.f;

    load_slab(0, 0);
    load_slab(1, 1);

    for (int s = 0; s < 32; s++) {
        CP_WAIT1();
        __syncthreads();
        const float* Ab = sm + (s & 1) * STAGE_FL;
        const float* Bb = Ab + 128 * GS;

#pragma unroll
        for (int kk = 0; kk < 4; kk++) {
            uint32_t af[2][4];
#pragma unroll
            for (int mt = 0; mt < 2; mt++) {
                const float* p = Ab + (wm + mt * 16) * GS + kk * 8;
                af[mt][0] = fbits(p[g * GS + t]);
                af[mt][1] = fbits(p[(g + 8) * GS + t]);
                af[mt][2] = fbits(p[g * GS + t + 4]);
                af[mt][3] = fbits(p[(g + 8) * GS + t + 4]);
            }
#pragma unroll
            for (int nt = 0; nt < 8; nt++) {
                uint32_t bf[2];
                const float* p = Bb + (wn + nt * 8 + g) * GS + kk * 8;
                bf[0] = fbits(p[t]);
                bf[1] = fbits(p[t + 4]);
                mma8(acc[0][nt], af[0], bf);
                mma8(acc[1][nt], af[1], bf);
            }
        }
        __syncthreads();
        if (s + 2 < 32) load_slab(s + 2, s & 1);
        else CP_COMMIT();   // empty group keeps wait_group counting consistent
    }

    // Epilogue: bias add (+ tf32 round for QKV), scatter/store.
#pragma unroll
    for (int mt = 0; mt < 2; mt++) {
        const int mr = m0 + wm + mt * 16 + g;   // rows mr, mr+8
#pragma unroll
        for (int nt = 0; nt < 8; nt++) {
            const int nc = n0 + wn + nt * 8 + 2 * t;
            const float2 bb = *(const float2*)&bias[nc];
            float v0 = acc[mt][nt][0] + bb.x;
            float v1 = acc[mt][nt][1] + bb.y;
            float v2 = acc[mt][nt][2] + bb.x;
            float v3 = acc[mt][nt][3] + bb.y;
            if (QKV) {
                v0 = rtf32(v0); v1 = rtf32(v1); v2 = rtf32(v2); v3 = rtf32(v3);
                const int h = nc >> 6, c = nc & 63;
                const int b0i = mr >> 11, nn0 = mr & (NSEQ - 1);
                const int b1i = (mr + 8) >> 11, nn1 = (mr + 8) & (NSEQ - 1);
                *(float2*)&out[(((size_t)(b0i * NH + h) * NSEQ + nn0) << 6) + c] =
                    make_float2(v0, v1);
                *(float2*)&out[(((size_t)(b1i * NH + h) * NSEQ + nn1) << 6) + c] =
                    make_float2(v2, v3);
            } else {
                *(float2*)&out[(size_t)mr * EDIM + nc]       = make_float2(v0, v1);
                *(float2*)&out[(size_t)(mr + 8) * EDIM + nc] = make_float2(v2, v3);
            }
        }
    }
}

// ---------------------------------------------------------------------------
// Flash attention with tf32 mma.sync.
// CTA = one (b,h) x 64-query tile, 128 threads (4 warps, one m16 band each).
// Q frags register-resident; K/V tiles in smem; P via per-warp smem (reuses
// the Q staging region) to form A-fragments for P@V.
// smem strides: Q/P 68 (68%32=4 -> conflict-free), V 72 (72%32=8).
// ---------------------------------------------------------------------------
#define QS 68
#define VS 72
#define ATTN_SMEM ((2 * 64 * QS + 64 * VS) * 4)   // 53248 B

__global__ __launch_bounds__(128)
void attn_mma()
{
    extern __shared__ __align__(16) float asm_[];
    float* sq = asm_;                 // [64][QS]  Q staging, then per-warp P
    float* sk = asm_ + 64 * QS;       // [64][QS]
    float* sv = asm_ + 2 * 64 * QS;   // [64][VS]

    const int tid = threadIdx.x, lane = tid & 31, w = tid >> 5;
    const int g = lane >> 2, t = lane & 3;
    const int bh = blockIdx.y, q0 = blockIdx.x << 6;

    const float* qh = g_q + (size_t)bh * NSEQ * CHD;
    const float* kh = g_k + (size_t)bh * NSEQ * CHD;
    const float* vh = g_v + (size_t)bh * NSEQ * CHD;

    // Stage Q (scaled by 0.125 = 2^-3, exact in tf32), then pull A-frags.
#pragma unroll
    for (int i = 0; i < 8; i++) {
        const int idx = tid + (i << 7);          // 0..1023
        const int row = idx >> 4, seg = idx & 15;
        float4 v = *(const float4*)&qh[(size_t)(q0 + row) * CHD + seg * 4];
        v.x *= 0.125f; v.y *= 0.125f; v.z *= 0.125f; v.w *= 0.125f;
        *(float4*)&sq[row * QS + seg * 4] = v;
    }
    __syncthreads();

    uint32_t qa[8][4];
    {
        const float* qb = sq + (w * 16) * QS;
#pragma unroll
        for (int kk = 0; kk < 8; kk++) {
            qa[kk][0] = fbits(qb[g * QS + kk * 8 + t]);
            qa[kk][1] = fbits(qb[(g + 8) * QS + kk * 8 + t]);
            qa[kk][2] = fbits(qb[g * QS + kk * 8 + t + 4]);
            qa[kk][3] = fbits(qb[(g + 8) * QS + kk * 8 + t + 4]);
        }
    }
    __syncthreads();                   // Q region now reusable as P
    float* Pw = sq + (w * 16) * QS;    // per-warp P [16][QS]

    float mr0 = -CUDART_INF_F, mr1 = -CUDART_INF_F;
    float l0 = 0.f, l1 = 0.f;
    float o[8][4];
#pragma unroll
    for (int nt = 0; nt < 8; nt++)
#pragma unroll
        for (int r = 0; r < 4; r++) o[nt][r] = 0.f;

    for (int kv0 = 0; kv0 < NSEQ; kv0 += 64) {
        // Fill K and V tiles.
#pragma unroll
        for (int i = 0; i < 8; i++) {
            const int idx = tid + (i << 7);
            const int row = idx >> 4, seg = idx & 15;
            *(float4*)&sk[row * QS + seg * 4] =
                *(const float4*)&kh[(size_t)(kv0 + row) * CHD + seg * 4];
            *(float4*)&sv[row * VS + seg * 4] =
                *(const float4*)&vh[(size_t)(kv0 + row) * CHD + seg * 4];
        }
        __syncthreads();

        // S = Q @ K^T  (C-frag: rows g/g+8 of warp band, cols nt*8+2t{,+1})
        float s[8][4];
#pragma unroll
        for (int nt = 0; nt < 8; nt++)
#pragma unroll
            for (int r = 0; r < 4; r++) s[nt][r] = 0.f;

#pragma unroll
        for (int kk = 0; kk < 8; kk++) {
#pragma unroll
            for (int nt = 0; nt < 8; nt++) {
                uint32_t bf[2];
                const float* p = sk + (nt * 8 + g) * QS + kk * 8;
                bf[0] = fbits(p[t]);
                bf[1] = fbits(p[t + 4]);
                mma8(s[nt], qa[kk], bf);
            }
        }

        // Online softmax (rows g and g+8; reductions across 4-lane group).
        float mx0 = -CUDART_INF_F, mx1 = -CUDART_INF_F;
#pragma unroll
        for (int nt = 0; nt < 8; nt++) {
            mx0 = fmaxf(mx0, fmaxf(s[nt][0], s[nt][1]));
            mx1 = fmaxf(mx1, fmaxf(s[nt][2], s[nt][3]));
        }
        mx0 = fmaxf(mx0, __shfl_xor_sync(0xffffffffu, mx0, 1));
        mx0 = fmaxf(mx0, __shfl_xor_sync(0xffffffffu, mx0, 2));
        mx1 = fmaxf(mx1, __shfl_xor_sync(0xffffffffu, mx1, 1));
        mx1 = fmaxf(mx1, __shfl_xor_sync(0xffffffffu, mx1, 2));

        const float mn0 = fmaxf(mr0, mx0), mn1 = fmaxf(mr1, mx1);
        const float al0 = __expf(mr0 - mn0), al1 = __expf(mr1 - mn1);
        float sum0 = 0.f, sum1 = 0.f;
#pragma unroll
        for (int nt = 0; nt < 8; nt++) {
            s[nt][0] = __expf(s[nt][0] - mn0); sum0 += s[nt][0];
            s[nt][1] = __expf(s[nt][1] - mn0); sum0 += s[nt][1];
            s[nt][2] = __expf(s[nt][2] - mn1); sum1 += s[nt][2];
            s[nt][3] = __expf(s[nt][3] - mn1); sum1 += s[nt][3];
        }
        sum0 += __shfl_xor_sync(0xffffffffu, sum0, 1);
        sum0 += __shfl_xor_sync(0xffffffffu, sum0, 2);
        sum1 += __shfl_xor_sync(0xffffffffu, sum1, 1);
        sum1 += __shfl_xor_sync(0xffffffffu, sum1, 2);
        l0 = l0 * al0 + sum0;  mr0 = mn0;
        l1 = l1 * al1 + sum1;  mr1 = mn1;

#pragma unroll
        for (int nt = 0; nt < 8; nt++) {
            o[nt][0] *= al0; o[nt][1] *= al0;
            o[nt][2] *= al1; o[nt][3] *= al1;
            // Write P (tf32-rounded) to per-warp smem.
            const int c = nt * 8 + 2 * t;
            *(float2*)&Pw[g * QS + c] =
                make_float2(rtf32(s[nt][0]), rtf32(s[nt][1]));
            *(float2*)&Pw[(g + 8) * QS + c] =
                make_float2(rtf32(s[nt][2]), rtf32(s[nt][3]));
        }
        __syncwarp();

        // O += P @ V
#pragma unroll
        for (int kk = 0; kk < 8; kk++) {
            uint32_t pa[4];
            pa[0] = fbits(Pw[g * QS + kk * 8 + t]);
            pa[1] = fbits(Pw[(g + 8) * QS + kk * 8 + t]);
            pa[2] = fbits(Pw[g * QS + kk * 8 + t + 4]);
            pa[3] = fbits(Pw[(g + 8) * QS + kk * 8 + t + 4]);
#pragma unroll
            for (int nt = 0; nt < 8; nt++) {
                uint32_t bf[2];
                bf[0] = fbits(sv[(kk * 8 + t) * VS + nt * 8 + g]);
                bf[1] = fbits(sv[(kk * 8 + t + 4) * VS + nt * 8 + g]);
                mma8(o[nt], pa, bf);
            }
        }
        __syncthreads();   // done reading sk/sv before next fill
    }

    // Normalize, round (consumed by tf32 out-proj), write [b, n, h*c].
    const float inv0 = 1.f / l0, inv1 = 1.f / l1;
    const int b = bh >> 4, h = bh & 15;
    const int n_0 = q0 + w * 16 + g;
    float* ob = g_attn + (size_t)b * NSEQ * EDIM + h * 64;
#pragma unroll
    for (int nt = 0; nt < 8; nt++) {
        const int c = nt * 8 + 2 * t;
        *(float2*)&ob[(size_t)n_0 * EDIM + c] =
            make_float2(rtf32(o[nt][0] * inv0), rtf32(o[nt][1] * inv0));
        *(float2*)&ob[(size_t)(n_0 + 8) * EDIM + c] =
            make_float2(rtf32(o[nt][2] * inv1), rtf32(o[nt][3] * inv1));
    }
}

// ---------------------------------------------------------------------------
// Launch
// ---------------------------------------------------------------------------
extern "C" void kernel_launch(void* const* d_in, const int* in_sizes, int n_in,
                              void* d_out, int out_size)
{
    const float* x  = (const float*)d_in[0];
    const float* Wq = (const float*)d_in[1];
    const float* bq = (const float*)d_in[2];
    const float* Wk = (const float*)d_in[3];
    const float* bk = (const float*)d_in[4];
    const float* Wv = (const float*)d_in[5];
    const float* bv = (const float*)d_in[6];
    const float* Wo = (const float*)d_in[7];
    const float* bo = (const float*)d_in[8];
    float* out = (float*)d_out;

    float *qp, *kp, *vp, *ap, *xr, *wr;
    cudaGetSymbolAddress((void**)&qp, g_q);
    cudaGetSymbolAddress((void**)&kp, g_k);
    cudaGetSymbolAddress((void**)&vp, g_v);
    cudaGetSymbolAddress((void**)&ap, g_attn);
    cudaGetSymbolAddress((void**)&xr, g_xr);
    cudaGetSymbolAddress((void**)&wr, g_wr);

    cudaFuncSetAttribute(gemm_mma<1>,
                         cudaFuncAttributeMaxDynamicSharedMemorySize, GSMEM);
    cudaFuncSetAttribute(gemm_mma<0>,
                         cudaFuncAttributeMaxDynamicSharedMemorySize, GSMEM);
    cudaFuncSetAttribute(attn_mma,
                         cudaFuncAttributeMaxDynamicSharedMemorySize, ATTN_SMEM);

    // Pre-round operands to tf32 (RN) so hot loops pass raw bits.
    const int XN4 = MTOT * EDIM / 4, WN4 = EDIM * EDIM / 4;
    round_tf32_kernel<<<(XN4 + 255) / 256, 256>>>(x, xr, XN4);
    round_tf32_kernel<<<(WN4 + 255) / 256, 256>>>(Wq, wr + 0 * EDIM * EDIM, WN4);
    round_tf32_kernel<<<(WN4 + 255) / 256, 256>>>(Wk, wr + 1 * EDIM * EDIM, WN4);
    round_tf32_kernel<<<(WN4 + 255) / 256, 256>>>(Wv, wr + 2 * EDIM * EDIM, WN4);
    round_tf32_kernel<<<(WN4 + 255) / 256, 256>>>(Wo, wr + 3 * EDIM * EDIM, WN4);

    dim3 ggrid(EDIM / 128, MTOT / 128);   // (8, 64)
    gemm_mma<1><<<ggrid, 256, GSMEM>>>(xr, wr + 0 * EDIM * EDIM, bq, qp);
    gemm_mma<1><<<ggrid, 256, GSMEM>>>(xr, wr + 1 * EDIM * EDIM, bk, kp);
    gemm_mma<1><<<ggrid, 256, GSMEM>>>(xr, wr + 2 * EDIM * EDIM, bv, vp);

    attn_mma<<<dim3(NSEQ / 64, BATCH * NH), 128, ATTN_SMEM>>>();

    gemm_mma<0><<<ggrid, 256, GSMEM>>>(ap, wr + 3 * EDIM * EDIM, bo, out);
}

// round 4
// speedup vs baseline: 10.0390x; 2.0080x over previous
#include <cuda_runtime.h>
#include <cuda_fp16.h>
#include <math_constants.h>
#include <cstdint>

#define BATCH 4
#define NSEQ  2048
#define EDIM  1024
#define NH    16
#define CHD   64
#define MTOT  (BATCH * NSEQ)   // 8192

// f16 scratch (allocation-free: __device__ globals).
__device__ __half g_xh[MTOT * EDIM];       // x, f16
__device__ __half g_wh[4][EDIM * EDIM];    // Wq,Wk,Wv,Wo, f16
__device__ __half g_qh[MTOT * EDIM];       // [b,h,n,c], pre-scaled by 0.125
__device__ __half g_kh[MTOT * EDIM];       // [b,h,n,c]
__device__ __half g_vh[MTOT * EDIM];       // [b,h,n,c]
__device__ __half g_ah[MTOT * EDIM];       // [b,n,h*c]

// ---------------------------------------------------------------------------
// Helpers
// ---------------------------------------------------------------------------
__device__ __forceinline__ uint32_t smem_u32(const void* p) {
    uint32_t a;
    asm("{ .reg .u64 t; cvta.to.shared.u64 t, %1; cvt.u32.u64 %0, t; }"
        : "=r"(a) : "l"(p));
    return a;
}

// pack two f32 -> f16x2 (lo = first arg, at lower halfword)
__device__ __forceinline__ uint32_t packh2(float lo, float hi) {
    uint32_t r;
    asm("cvt.rn.f16x2.f32 %0, %1, %2;" : "=r"(r) : "f"(hi), "f"(lo));
    return r;
}

// D += A @ B  (m16n8k16, f16 in, f32 accumulate)
__device__ __forceinline__ void mma16(float* c, const uint32_t* a, const uint32_t* b) {
    asm volatile(
        "mma.sync.aligned.m16n8k16.row.col.f32.f16.f16.f32 "
        "{%0,%1,%2,%3}, {%4,%5,%6,%7}, {%8,%9}, {%0,%1,%2,%3};"
        : "+f"(c[0]), "+f"(c[1]), "+f"(c[2]), "+f"(c[3])
        : "r"(a[0]), "r"(a[1]), "r"(a[2]), "r"(a[3]), "r"(b[0]), "r"(b[1]));
}

#define LDMX4(r, addr) \
    asm volatile("ldmatrix.sync.aligned.m8n8.x4.shared.b16 {%0,%1,%2,%3}, [%4];" \
        : "=r"((r)[0]), "=r"((r)[1]), "=r"((r)[2]), "=r"((r)[3]) : "r"(addr))

#define LDMX4T(r0, r1, r2, r3, addr) \
    asm volatile("ldmatrix.sync.aligned.m8n8.x4.trans.shared.b16 {%0,%1,%2,%3}, [%4];" \
        : "=r"(r0), "=r"(r1), "=r"(r2), "=r"(r3) : "r"(addr))

#define CP_ASYNC16(dst, src) \
    asm volatile("cp.async.cg.shared.global [%0], [%1], 16;" :: "r"(dst), "l"(src))
#define CP_COMMIT() asm volatile("cp.async.commit_group;" ::: "memory")
#define CP_WAIT1()  asm volatile("cp.async.wait_group 1;" ::: "memory")
#define CP_WAIT0()  asm volatile("cp.async.wait_group 0;" ::: "memory")

// ---------------------------------------------------------------------------
// Fused f32 -> f16 convert: x and the four weight matrices, one launch.
// 8 elems per thread. Layout: [x (8M) | Wq | Wk | Wv | Wo (1M each)].
// ---------------------------------------------------------------------------
#define X8 (MTOT * EDIM / 8)           // 1048576
#define W8 (EDIM * EDIM / 8)           // 131072

__global__ void cvt_h_kernel(const float* __restrict__ x,
                             const float* __restrict__ w0, const float* __restrict__ w1,
                             const float* __restrict__ w2, const float* __restrict__ w3)
{
    const int i = blockIdx.x * blockDim.x + threadIdx.x;
    const float* src; __half* dst; size_t j;
    if (i < X8) { src = x; dst = g_xh; j = (size_t)i << 3; }
    else {
        const int k = i - X8;
        const int r = k >> 17;                 // /131072
        j = (size_t)(k & (W8 - 1)) << 3;
        src = (r == 0) ? w0 : (r == 1) ? w1 : (r == 2) ? w2 : w3;
        dst = g_wh[r];
    }
    const float4 a = *(const float4*)(src + j);
    const float4 b = *(const float4*)(src + j + 4);
    uint4 o;
    o.x = packh2(a.x, a.y); o.y = packh2(a.z, a.w);
    o.z = packh2(b.x, b.y); o.w = packh2(b.z, b.w);
    *(uint4*)(dst + j) = o;
}

// ---------------------------------------------------------------------------
// f16 NT GEMM: C[M,N] = A[M,K] @ W[N,K]^T + bias.  M=8192, N=K=1024.
// 128x128 CTA tile, BK=32, 8 warps (32x64 warp tiles), double-buffered
// cp.async, ldmatrix fragments. Smem row stride 40 halves (80B = 20 words:
// conflict-free ldmatrix).
// MODE 0: fused QKV (blockIdx.z selects W/bias/dst; Q scaled 0.125, f16 out,
//         scattered to [b,h,n,c]).  MODE 1: out-proj, f32 out to d_out.
// ---------------------------------------------------------------------------
#define GSTR  40
#define GTILE (128 * GSTR)

template <int MODE>
__global__ __launch_bounds__(256)
void gemm_h(const float* __restrict__ bias0, const float* __restrict__ bias1,
            const float* __restrict__ bias2, float* __restrict__ outp)
{
    __shared__ __half sA[2][GTILE];
    __shared__ __half sB[2][GTILE];

    const int tid = threadIdx.x, lane = tid & 31, wid = tid >> 5;
    const int g = lane >> 2, t = lane & 3;
    const int lrow = lane & 15, lhi = lane >> 4;
    const int m0 = blockIdx.y << 7, n0 = blockIdx.x << 7;
    const int wm = (wid >> 1) << 5, wn = (wid & 1) << 6;

    const __half* A; const __half* W; const float* bias;
    if (MODE == 0) {
        const int z = blockIdx.z;
        A = g_xh; W = g_wh[z];
        bias = (z == 0) ? bias0 : (z == 1) ? bias1 : bias2;
    } else {
        A = g_ah; W = g_wh[3]; bias = bias0;
    }

    auto load_slab = [&](int s, int buf) {
        const int k0 = s << 5;
#pragma unroll
        for (int i = 0; i < 2; i++) {
            const int idx = tid + (i << 8);          // 0..511
            const int row = idx >> 2, c4 = idx & 3;
            CP_ASYNC16(smem_u32(&sA[buf][row * GSTR + c4 * 8]),
                       A + (size_t)(m0 + row) * EDIM + k0 + c4 * 8);
            CP_ASYNC16(smem_u32(&sB[buf][row * GSTR + c4 * 8]),
                       W + (size_t)(n0 + row) * EDIM + k0 + c4 * 8);
        }
        CP_COMMIT();
    };

    float acc[2][8][4];
#pragma unroll
    for (int mt = 0; mt < 2; mt++)
#pragma unroll
        for (int o = 0; o < 8; o++)
#pragma unroll
            for (int r = 0; r < 4; r++) acc[mt][o][r] = 0.f;

    load_slab(0, 0);
    load_slab(1, 1);

    for (int s = 0; s < 32; s++) {
        CP_WAIT1();
        __syncthreads();
        const __half* Ab = sA[s & 1];
        const __half* Bb = sB[s & 1];

#pragma unroll
        for (int ks = 0; ks < 2; ks++) {
            uint32_t af[2][4];
#pragma unroll
            for (int mt = 0; mt < 2; mt++)
                LDMX4(af[mt], smem_u32(Ab + (wm + mt * 16 + lrow) * GSTR
                                          + ks * 16 + lhi * 8));
            uint32_t bf[8][2];
#pragma unroll
            for (int nb = 0; nb < 4; nb++) {
                uint32_t r0, r1, r2, r3;
                uint32_t addr = smem_u32(Bb + (wn + nb * 16 + lrow) * GSTR
                                            + ks * 16 + lhi * 8);
                asm volatile("ldmatrix.sync.aligned.m8n8.x4.shared.b16 "
                             "{%0,%1,%2,%3}, [%4];"
                             : "=r"(r0), "=r"(r1), "=r"(r2), "=r"(r3) : "r"(addr));
                bf[2 * nb][0] = r0;     bf[2 * nb][1] = r2;
                bf[2 * nb + 1][0] = r1; bf[2 * nb + 1][1] = r3;
            }
#pragma unroll
            for (int o = 0; o < 8; o++) {
                mma16(acc[0][o], af[0], bf[o]);
                mma16(acc[1][o], af[1], bf[o]);
            }
        }
        __syncthreads();
        if (s + 2 < 32) load_slab(s + 2, s & 1);
        else CP_COMMIT();
    }

    // Epilogue
#pragma unroll
    for (int mt = 0; mt < 2; mt++) {
        const int mr = m0 + wm + mt * 16 + g;
#pragma unroll
        for (int o = 0; o < 8; o++) {
            const int nc = n0 + wn + o * 8 + 2 * t;
            const float2 bb = *(const float2*)&bias[nc];
            const float v0 = acc[mt][o][0] + bb.x;
            const float v1 = acc[mt][o][1] + bb.y;
            const float v2 = acc[mt][o][2] + bb.x;
            const float v3 = acc[mt][o][3] + bb.y;
            if (MODE == 0) {
                const int z = blockIdx.z;
                const float sc = (z == 0) ? 0.125f : 1.f;
                __half* oh = (z == 0) ? g_qh : (z == 1) ? g_kh : g_vh;
                const int h = nc >> 6, c = nc & 63;
                const int b0i = mr >> 11, nn0 = mr & (NSEQ - 1);
                const int b1i = (mr + 8) >> 11, nn1 = (mr + 8) & (NSEQ - 1);
                *(uint32_t*)&oh[(((size_t)(b0i * NH + h) * NSEQ + nn0) << 6) + c] =
                    packh2(v0 * sc, v1 * sc);
                *(uint32_t*)&oh[(((size_t)(b1i * NH + h) * NSEQ + nn1) << 6) + c] =
                    packh2(v2 * sc, v3 * sc);
            } else {
                *(float2*)&outp[(size_t)mr * EDIM + nc]       = make_float2(v0, v1);
                *(float2*)&outp[(size_t)(mr + 8) * EDIM + nc] = make_float2(v2, v3);
            }
        }
    }
}

// ---------------------------------------------------------------------------
// f16 flash attention. CTA = one (b,h) x 64-query tile, 128 threads (4 warps,
// one m16 band each). Q frags register-resident (ldmatrix); K/V tiles SW128-
// swizzled in smem, double-buffered cp.async. S C-frags repack in-register to
// PV A-frags (no smem round-trip); V loaded as B via ldmatrix.trans.
// ---------------------------------------------------------------------------
__device__ __forceinline__ uint32_t swz_off(int row, int ch) {
    return (uint32_t)(row * 64 + ((ch ^ (row & 7)) << 3));   // halves
}

__global__ __launch_bounds__(128)
void attn_h()
{
    __shared__ __half sQ[64 * 64];
    __shared__ __half sK[2][64 * 64];
    __shared__ __half sV[2][64 * 64];

    const int tid = threadIdx.x, lane = tid & 31, w = tid >> 5;
    const int g = lane >> 2, t = lane & 3;
    const int lrow = lane & 15, lhi = lane >> 4;
    const int bh = blockIdx.y, q0 = blockIdx.x << 6;

    const __half* qh = g_qh + (size_t)bh * NSEQ * CHD;
    const __half* kh = g_kh + (size_t)bh * NSEQ * CHD;
    const __half* vh = g_vh + (size_t)bh * NSEQ * CHD;

    // Stage Q (already scaled by 0.125 at projection time).
#pragma unroll
    for (int i = 0; i < 4; i++) {
        const int idx = tid + (i << 7);
        const int row = idx >> 3, ch = idx & 7;
        CP_ASYNC16(smem_u32(&sQ[swz_off(row, ch)]),
                   qh + (size_t)(q0 + row) * CHD + ch * 8);
    }
    CP_COMMIT();

    auto loadkv = [&](int it, int buf) {
        const int r0 = it << 6;
#pragma unroll
        for (int i = 0; i < 4; i++) {
            const int idx = tid + (i << 7);
            const int row = idx >> 3, ch = idx & 7;
            CP_ASYNC16(smem_u32(&sK[buf][swz_off(row, ch)]),
                       kh + (size_t)(r0 + row) * CHD + ch * 8);
            CP_ASYNC16(smem_u32(&sV[buf][swz_off(row, ch)]),
                       vh + (size_t)(r0 + row) * CHD + ch * 8);
        }
        CP_COMMIT();
    };

    loadkv(0, 0);
    CP_WAIT0();
    __syncthreads();

    // Q A-fragments for 4 k16-groups.
    uint32_t qa[4][4];
#pragma unroll
    for (int kk = 0; kk < 4; kk++) {
        const int row = w * 16 + lrow;
        LDMX4(qa[kk], smem_u32(&sQ[swz_off(row, kk * 2 + lhi)]));
    }

    float mr0 = -CUDART_INF_F, mr1 = -CUDART_INF_F, l0 = 0.f, l1 = 0.f;
    float o[8][4];
#pragma unroll
    for (int nt = 0; nt < 8; nt++)
#pragma unroll
        for (int r = 0; r < 4; r++) o[nt][r] = 0.f;

    for (int it = 0; it < 32; it++) {
        if (it + 1 < 32) { loadkv(it + 1, (it + 1) & 1); CP_WAIT1(); }
        else CP_WAIT0();
        __syncthreads();
        const __half* K = sK[it & 1];
        const __half* V = sV[it & 1];

        // S = Q @ K^T
        float s[8][4];
#pragma unroll
        for (int nt = 0; nt < 8; nt++)
#pragma unroll
            for (int r = 0; r < 4; r++) s[nt][r] = 0.f;

#pragma unroll
        for (int kk = 0; kk < 4; kk++) {
            uint32_t bf[8][2];
#pragma unroll
            for (int nb = 0; nb < 4; nb++) {
                uint32_t r0, r1, r2, r3;
                const int row = nb * 16 + lrow;
                uint32_t addr = smem_u32(K + swz_off(row, kk * 2 + lhi));
                asm volatile("ldmatrix.sync.aligned.m8n8.x4.shared.b16 "
                             "{%0,%1,%2,%3}, [%4];"
                             : "=r"(r0), "=r"(r1), "=r"(r2), "=r"(r3) : "r"(addr));
                bf[2 * nb][0] = r0;     bf[2 * nb][1] = r2;
                bf[2 * nb + 1][0] = r1; bf[2 * nb + 1][1] = r3;
            }
#pragma unroll
            for (int nt = 0; nt < 8; nt++) mma16(s[nt], qa[kk], bf[nt]);
        }

        // Online softmax (rows g, g+8; reductions across 4-lane groups).
        float mx0 = -CUDART_INF_F, mx1 = -CUDART_INF_F;
#pragma unroll
        for (int nt = 0; nt < 8; nt++) {
            mx0 = fmaxf(mx0, fmaxf(s[nt][0], s[nt][1]));
            mx1 = fmaxf(mx1, fmaxf(s[nt][2], s[nt][3]));
        }
        mx0 = fmaxf(mx0, __shfl_xor_sync(0xffffffffu, mx0, 1));
        mx0 = fmaxf(mx0, __shfl_xor_sync(0xffffffffu, mx0, 2));
        mx1 = fmaxf(mx1, __shfl_xor_sync(0xffffffffu, mx1, 1));
        mx1 = fmaxf(mx1, __shfl_xor_sync(0xffffffffu, mx1, 2));

        const float mn0 = fmaxf(mr0, mx0), mn1 = fmaxf(mr1, mx1);
        const float al0 = __expf(mr0 - mn0), al1 = __expf(mr1 - mn1);
        float sum0 = 0.f, sum1 = 0.f;
#pragma unroll
        for (int nt = 0; nt < 8; nt++) {
            s[nt][0] = __expf(s[nt][0] - mn0); sum0 += s[nt][0];
            s[nt][1] = __expf(s[nt][1] - mn0); sum0 += s[nt][1];
            s[nt][2] = __expf(s[nt][2] - mn1); sum1 += s[nt][2];
            s[nt][3] = __expf(s[nt][3] - mn1); sum1 += s[nt][3];
        }
        sum0 += __shfl_xor_sync(0xffffffffu, sum0, 1);
        sum0 += __shfl_xor_sync(0xffffffffu, sum0, 2);
        sum1 += __shfl_xor_sync(0xffffffffu, sum1, 1);
        sum1 += __shfl_xor_sync(0xffffffffu, sum1, 2);
        l0 = l0 * al0 + sum0;  mr0 = mn0;
        l1 = l1 * al1 + sum1;  mr1 = mn1;

#pragma unroll
        for (int nt = 0; nt < 8; nt++) {
            o[nt][0] *= al0; o[nt][1] *= al0;
            o[nt][2] *= al1; o[nt][3] *= al1;
        }

        // P C-frag -> f16 A-frags, all in registers.
        uint32_t pa[4][4];
#pragma unroll
        for (int kk = 0; kk < 4; kk++) {
            pa[kk][0] = packh2(s[2 * kk][0],     s[2 * kk][1]);
            pa[kk][1] = packh2(s[2 * kk][2],     s[2 * kk][3]);
            pa[kk][2] = packh2(s[2 * kk + 1][0], s[2 * kk + 1][1]);
            pa[kk][3] = packh2(s[2 * kk + 1][2], s[2 * kk + 1][3]);
        }

        // O += P @ V  (V via ldmatrix.trans as col-major B)
#pragma unroll
        for (int kk = 0; kk < 4; kk++) {
            const int row_k = kk * 16 + ((lane >> 3) & 1) * 8 + (lane & 7);
#pragma unroll
            for (int ci = 0; ci < 4; ci++) {
                uint32_t r0, r1, r2, r3;
                uint32_t addr = smem_u32(V + swz_off(row_k, ci * 2 + lhi));
                LDMX4T(r0, r1, r2, r3, addr);
                uint32_t b0[2] = {r0, r1}, b1[2] = {r2, r3};
                mma16(o[ci * 2],     pa[kk], b0);
                mma16(o[ci * 2 + 1], pa[kk], b1);
            }
        }
        __syncthreads();   // compute done before next fill overwrites buffer
    }

    // Normalize, convert to f16, write [b, n, h*c].
    const float inv0 = 1.f / l0, inv1 = 1.f / l1;
    const int b = bh >> 4, h = bh & 15;
    const int nq = q0 + w * 16 + g;
    __half* ob = g_ah + (size_t)b * NSEQ * EDIM + h * 64;
#pragma unroll
    for (int nt = 0; nt < 8; nt++) {
        const int c = nt * 8 + 2 * t;
        *(uint32_t*)&ob[(size_t)nq * EDIM + c] =
            packh2(o[nt][0] * inv0, o[nt][1] * inv0);
        *(uint32_t*)&ob[(size_t)(nq + 8) * EDIM + c] =
            packh2(o[nt][2] * inv1, o[nt][3] * inv1);
    }
}

// ---------------------------------------------------------------------------
// Launch
// ---------------------------------------------------------------------------
extern "C" void kernel_launch(void* const* d_in, const int* in_sizes, int n_in,
                              void* d_out, int out_size)
{
    const float* x  = (const float*)d_in[0];
    const float* Wq = (const float*)d_in[1];
    const float* bq = (const float*)d_in[2];
    const float* Wk = (const float*)d_in[3];
    const float* bk = (const float*)d_in[4];
    const float* Wv = (const float*)d_in[5];
    const float* bv = (const float*)d_in[6];
    const float* Wo = (const float*)d_in[7];
    const float* bo = (const float*)d_in[8];
    float* out = (float*)d_out;

    // 1) convert x + all weights to f16 (one launch)
    const int NCVT = X8 + 4 * W8;              // 1572864 threads
    cvt_h_kernel<<<NCVT / 256, 256>>>(x, Wq, Wk, Wv, Wo);

    // 2) fused QKV projection (z = 0,1,2 -> Q,K,V)
    gemm_h<0><<<dim3(EDIM / 128, MTOT / 128, 3), 256>>>(bq, bk, bv, nullptr);

    // 3) attention
    attn_h<<<dim3(NSEQ / 64, BATCH * NH), 128>>>();

    // 4) output projection (f32 out)
    gemm_h<1><<<dim3(EDIM / 128, MTOT / 128), 256>>>(bo, nullptr, nullptr, out);
}